// round 17
// baseline (speedup 1.0000x reference)
#include <cuda_runtime.h>
#include <cuda.h>
#include <cuda_bf16.h>
#include <cstdint>
#include <dlfcn.h>

#define T 1024
#define H 1024
#define F 768
#define E 32
#define K 4

#define MAXTILES 64
#define PITCH_B 80
#define PLANE_B 10240
#define BPAIR 20480
#define PITCH_A 144          /* 16B-aligned, conflict-free: 144*r mod 128 = 16r */
#define ASLOT (128*PITCH_A)  /* 18432 */
#define NC1 32
#define NC2 24
#define ACT_TILE (NC2*BPAIR)

#define OFF_MBAR 0
/* gemm1 layout */
#define OFF_AP1  1024                     /* 2 x 18432 */
#define OFF_BP1  (OFF_AP1 + 2*ASLOT)      /* 2 x 20480 (also epilogue stage) */
#define OFF_RAW1 (OFF_BP1 + 2*BPAIR)      /* 2 x 16384 */
/* gemm2 layout */
#define OFF_AP2  1024                     /* 2 x 20480 */
#define OFF_BP2  (OFF_AP2 + 2*BPAIR)
#define OFF_RAW2 (OFF_BP2 + 2*BPAIR)
#define SMEM_TOTAL (OFF_RAW2 + 2*16384)   /* 115712 */

// ---------------- scratch ----------------
__device__ float    g_topk_w[T * K];
__device__ int      g_topk_id[T * K];
__device__ int      g_offset[E + 1];
__device__ int      g_tile_base[E];
__device__ int      g_ntiles[E];
__device__ int      g_assign_token[T * K];
__device__ int      g_row_of[T * K];
__device__ __align__(16) char g_hsc[(size_t)T * 4096];
__device__ __align__(16) char g_act[(size_t)MAXTILES * ACT_TILE];
__device__ float    g_y[(size_t)T * K * H];

// ---------------- helpers ----------------
__device__ __forceinline__ uint32_t smem_u32(const void* p) {
    uint32_t a;
    asm("{ .reg .u64 t; cvta.to.shared.u64 t, %1; cvt.u32.u64 %0, t; }" : "=r"(a) : "l"(p));
    return a;
}

#define MBAR_INIT(a, c) \
    asm volatile("mbarrier.init.shared.b64 [%0], %1;" :: "r"((uint32_t)(a)), "r"((uint32_t)(c)) : "memory")
#define MBAR_EXPECT(a, tx) \
    asm volatile("mbarrier.arrive.expect_tx.shared.b64 _, [%0], %1;" :: "r"((uint32_t)(a)), "r"((uint32_t)(tx)) : "memory")
#define MBAR_WAIT(a, ph) do { \
    asm volatile("{\n\t.reg .pred P;\n\tWL%=:\n\t" \
        "mbarrier.try_wait.parity.acquire.cta.shared::cta.b64 P, [%0], %1, 0x989680;\n\t" \
        "@P bra.uni WD%=;\n\tbra.uni WL%=;\n\tWD%=:\n\t}" \
        :: "r"((uint32_t)(a)), "r"((uint32_t)(ph)) : "memory"); } while (0)
#define BULK_G2S(dst, src, sz, mb) \
    asm volatile("cp.async.bulk.shared::cluster.global.mbarrier::complete_tx::bytes [%0], [%1], %2, [%3];" \
        :: "r"((uint32_t)(dst)), "l"(src), "r"((uint32_t)(sz)), "r"((uint32_t)(mb)) : "memory")
#define TMA2D(dst, map, x, y, mb) \
    asm volatile("cp.async.bulk.tensor.2d.shared::cta.global.tile.mbarrier::complete_tx::bytes " \
        "[%0], [%1, {%2, %3}], [%4];" \
        :: "r"((uint32_t)(dst)), "l"(map), "r"((int)(x)), "r"((int)(y)), "r"((uint32_t)(mb)) : "memory")

#define LDM4(r, addr) \
    asm volatile("ldmatrix.sync.aligned.m8n8.x4.shared.b16 {%0,%1,%2,%3}, [%4];" \
        : "=r"((r)[0]), "=r"((r)[1]), "=r"((r)[2]), "=r"((r)[3]) : "r"(addr))

#define MMA16816(d, a, b0, b1) \
    asm volatile("mma.sync.aligned.m16n8k16.row.col.f32.bf16.bf16.f32 " \
        "{%0,%1,%2,%3}, {%4,%5,%6,%7}, {%8,%9}, {%0,%1,%2,%3};" \
        : "+f"((d)[0]), "+f"((d)[1]), "+f"((d)[2]), "+f"((d)[3]) \
        : "r"((a)[0]), "r"((a)[1]), "r"((a)[2]), "r"((a)[3]), "r"(b0), "r"(b1))

__device__ __forceinline__ void cvt_split4(float4 v, uint2& hi, uint2& lo) {
    uint32_t h01, h23, l01, l23;
    asm("cvt.rn.bf16x2.f32 %0, %1, %2;" : "=r"(h01) : "f"(v.y), "f"(v.x));
    asm("cvt.rn.bf16x2.f32 %0, %1, %2;" : "=r"(h23) : "f"(v.w), "f"(v.z));
    float h0 = __uint_as_float(h01 << 16), h1 = __uint_as_float(h01 & 0xFFFF0000u);
    float h2 = __uint_as_float(h23 << 16), h3 = __uint_as_float(h23 & 0xFFFF0000u);
    asm("cvt.rn.bf16x2.f32 %0, %1, %2;" : "=r"(l01) : "f"(v.y - h1), "f"(v.x - h0));
    asm("cvt.rn.bf16x2.f32 %0, %1, %2;" : "=r"(l23) : "f"(v.w - h3), "f"(v.z - h2));
    hi = make_uint2(h01, h23);
    lo = make_uint2(l01, l23);
}

__device__ __forceinline__ float silu(float x) { return x / (1.f + __expf(-x)); }

// ---------------- router ----------------
__global__ void router_kernel(const float* __restrict__ hs,
                              const float* __restrict__ gw) {
    int warp = (blockIdx.x * blockDim.x + threadIdx.x) >> 5;
    int lane = threadIdx.x & 31;
    if (warp >= T) return;

    const float4* x4 = (const float4*)(hs + (size_t)warp * H);
    const float4* g4 = (const float4*)(gw + (size_t)lane * H);
    float acc = 0.f;
#pragma unroll 4
    for (int i = 0; i < H / 4; i++) {
        float4 xv = x4[i];
        float4 gv = g4[i];
        acc += xv.x * gv.x + xv.y * gv.y + xv.z * gv.z + xv.w * gv.w;
    }
    float m = acc;
#pragma unroll
    for (int o = 16; o; o >>= 1) m = fmaxf(m, __shfl_xor_sync(0xffffffffu, m, o));
    float p = __expf(acc - m);
    float s = p;
#pragma unroll
    for (int o = 16; o; o >>= 1) s += __shfl_xor_sync(0xffffffffu, s, o);
    float prob = p / s;

    float cur = prob;
    float wv[K];
    int   wid[K];
#pragma unroll
    for (int k = 0; k < K; k++) {
        float v = cur;
        int who = lane;
#pragma unroll
        for (int o = 16; o; o >>= 1) {
            float ov = __shfl_xor_sync(0xffffffffu, v, o);
            int   oi = __shfl_xor_sync(0xffffffffu, who, o);
            if (ov > v || (ov == v && oi < who)) { v = ov; who = oi; }
        }
        wv[k] = v;
        wid[k] = who;
        if (lane == who) cur = -1.f;
    }
    if (lane == 0) {
        float ws = wv[0] + wv[1] + wv[2] + wv[3];
        float inv = 1.f / ws;
#pragma unroll
        for (int k = 0; k < K; k++) {
            g_topk_w[warp * K + k]  = wv[k] * inv;
            g_topk_id[warp * K + k] = wid[k];
        }
    }
}

// ---------------- bucket ----------------
__global__ void bucket_kernel() {
    __shared__ int cnt[E];
    __shared__ int curp[E];
    __shared__ int offp[E + 1];
    int t = threadIdx.x;
    if (t < E) cnt[t] = 0;
    __syncthreads();
    int ids[K];
#pragma unroll
    for (int k = 0; k < K; k++) {
        ids[k] = g_topk_id[t * K + k];
        atomicAdd(&cnt[ids[k]], 1);
    }
    __syncthreads();
    if (t == 0) {
        int a = 0, tb = 0;
        for (int e = 0; e < E; e++) {
            offp[e] = a; curp[e] = a; a += cnt[e];
            int nt = (cnt[e] + 127) >> 7;
            g_ntiles[e] = nt;
            g_tile_base[e] = tb;
            tb += nt;
        }
        offp[E] = a;
    }
    __syncthreads();
#pragma unroll
    for (int k = 0; k < K; k++) {
        int pos = atomicAdd(&curp[ids[k]], 1);
        g_assign_token[pos] = t;
        g_row_of[t * K + k] = pos;
    }
    if (t <= E) g_offset[t] = offp[t];
}

// ---------------- hs -> per-token packed chunks: [t][c][hi64|lo64], elem k at byte 2k ----------------
__global__ void hs_pack_kernel(const float* __restrict__ hs) {
    int g = blockIdx.x * blockDim.x + threadIdx.x;
    int t = g >> 7;
    int c = (g >> 2) & 31;
    int q = g & 3;
    int k0 = c * 32 + q * 8;
    float4 v0 = *(const float4*)(hs + (size_t)t * H + k0);
    float4 v1 = *(const float4*)(hs + (size_t)t * H + k0 + 4);
    uint2 h0, l0, h1, l1;
    cvt_split4(v0, h0, l0);
    cvt_split4(v1, h1, l1);
    char* base = g_hsc + (size_t)t * 4096 + c * 128;
    *(uint2*)(base + q * 16)          = h0;
    *(uint2*)(base + q * 16 + 8)      = h1;
    *(uint2*)(base + 64 + q * 16)     = l0;
    *(uint2*)(base + 64 + q * 16 + 8) = l1;
}

// ---------------- shared pieces ----------------
__device__ __forceinline__ void convert_b(char* smem, int rawoff, int bpoff, int slot, int tid) {
    const char* rp = smem + rawoff + slot * 16384 + tid * 128;
    char* hp = smem + bpoff + slot * BPAIR + tid * PITCH_B;
#pragma unroll
    for (int q = 0; q < 8; q++) {
        int qq = (q + tid) & 7;
        float4 v = *(const float4*)(rp + qq * 16);
        uint2 hi, lo;
        cvt_split4(v, hi, lo);
        *(uint2*)(hp + qq * 8) = hi;
        *(uint2*)(hp + PLANE_B + qq * 8) = lo;
    }
}

// A pitch-144 (lo at +64); B pitch-80 planes
__device__ __forceinline__ void mma_phase_g1(uint32_t sb, int slot, int lane, int wm,
                                             const int brow[4], float acc[32][4]) {
    const uint32_t Ah = sb + OFF_AP1 + slot * ASLOT;
    const uint32_t Bh = sb + OFF_BP1 + slot * BPAIR;
#pragma unroll
    for (int ks = 0; ks < 2; ks++) {
        const uint32_t kb = ks * 32;
        const uint32_t lrow = (lane & 15), lcol = (lane >> 4) * 16;
        uint32_t ah[4][4], al[4][4];
#pragma unroll
        for (int i = 0; i < 4; i++) {
            uint32_t off = (uint32_t)((wm * 64 + i * 16 + lrow) * PITCH_A) + lcol + kb;
            LDM4(ah[i], Ah + off);
            LDM4(al[i], Ah + off + 64);
        }
        uint32_t bh[4][4], bl[4][4];
#pragma unroll
        for (int j2 = 0; j2 < 4; j2++) {
            uint32_t off = (uint32_t)((brow[j2] + lrow) * PITCH_B) + lcol + kb;
            LDM4(bh[j2], Bh + off);
            LDM4(bl[j2], Bh + PLANE_B + off);
        }
#pragma unroll
        for (int i = 0; i < 4; i++)
#pragma unroll
            for (int jt = 0; jt < 8; jt++) {
                int j2 = jt >> 1, hsel = jt & 1;
                MMA16816(acc[i * 8 + jt], ah[i], bh[j2][hsel], bh[j2][2 + hsel]);
            }
#pragma unroll
        for (int i = 0; i < 4; i++)
#pragma unroll
            for (int jt = 0; jt < 8; jt++) {
                int j2 = jt >> 1, hsel = jt & 1;
                MMA16816(acc[i * 8 + jt], ah[i], bl[j2][hsel], bl[j2][2 + hsel]);
            }
#pragma unroll
        for (int i = 0; i < 4; i++)
#pragma unroll
            for (int jt = 0; jt < 8; jt++) {
                int j2 = jt >> 1, hsel = jt & 1;
                MMA16816(acc[i * 8 + jt], al[i], bh[j2][hsel], bh[j2][2 + hsel]);
            }
    }
}

// both pitch-80 planes (gemm2)
__device__ __forceinline__ void mma_phase_g2(uint32_t sb, int slot, int lane, int wm,
                                             const int brow[4], float acc[32][4]) {
    const uint32_t Ah = sb + OFF_AP2 + slot * BPAIR;
    const uint32_t Bh = sb + OFF_BP2 + slot * BPAIR;
#pragma unroll
    for (int ks = 0; ks < 2; ks++) {
        const uint32_t kb = ks * 32;
        const uint32_t lrow = (lane & 15), lcol = (lane >> 4) * 16;
        uint32_t ah[4][4], al[4][4];
#pragma unroll
        for (int i = 0; i < 4; i++) {
            uint32_t off = (uint32_t)((wm * 64 + i * 16 + lrow) * PITCH_B) + lcol + kb;
            LDM4(ah[i], Ah + off);
            LDM4(al[i], Ah + PLANE_B + off);
        }
        uint32_t bh[4][4], bl[4][4];
#pragma unroll
        for (int j2 = 0; j2 < 4; j2++) {
            uint32_t off = (uint32_t)((brow[j2] + lrow) * PITCH_B) + lcol + kb;
            LDM4(bh[j2], Bh + off);
            LDM4(bl[j2], Bh + PLANE_B + off);
        }
#pragma unroll
        for (int i = 0; i < 4; i++)
#pragma unroll
            for (int jt = 0; jt < 8; jt++) {
                int j2 = jt >> 1, hsel = jt & 1;
                MMA16816(acc[i * 8 + jt], ah[i], bh[j2][hsel], bh[j2][2 + hsel]);
            }
#pragma unroll
        for (int i = 0; i < 4; i++)
#pragma unroll
            for (int jt = 0; jt < 8; jt++) {
                int j2 = jt >> 1, hsel = jt & 1;
                MMA16816(acc[i * 8 + jt], ah[i], bl[j2][hsel], bl[j2][2 + hsel]);
            }
#pragma unroll
        for (int i = 0; i < 4; i++)
#pragma unroll
            for (int jt = 0; jt < 8; jt++) {
                int j2 = jt >> 1, hsel = jt & 1;
                MMA16816(acc[i * 8 + jt], al[i], bh[j2][hsel], bh[j2][2 + hsel]);
            }
    }
}

// ================= GEMM1: A gathered per-row from g_hsc =================
__global__ __launch_bounds__(128, 1) void gemm1_mma(const __grid_constant__ CUtensorMap bmap) {
    const int e  = blockIdx.y >> 3;
    const int mt = blockIdx.y & 7;
    if (mt >= g_ntiles[e]) return;
    const int rbeg = g_offset[e], rend = g_offset[e + 1];
    const int row0 = rbeg + mt * 128;
    const int fbase = blockIdx.x * 64;
    const int tile = g_tile_base[e] + mt;

    extern __shared__ __align__(16) char smem[];
    const uint32_t sb = smem_u32(smem);
    const int tid = threadIdx.x, lane = tid & 31;
    const int wm = (tid >> 5) & 1, wn = tid >> 6;

    int rr = row0 + tid;
    int tok = g_assign_token[rr < rend ? rr : rbeg];
    const char* arow = g_hsc + (size_t)tok * 4096;

    int brow[4];
#pragma unroll
    for (int j2 = 0; j2 < 4; j2++)
        brow[j2] = (j2 < 2) ? (wn * 32 + j2 * 16) : (64 + wn * 32 + (j2 - 2) * 16);

    const int y0 = e * 2 * F + fbase;
    const int y1 = e * 2 * F + F + fbase;

    float acc[32][4];
#pragma unroll
    for (int i = 0; i < 32; i++)
#pragma unroll
        for (int j = 0; j < 4; j++) acc[i][j] = 0.f;

    if (tid == 0) {
        MBAR_INIT(sb + OFF_MBAR, 129);
        MBAR_INIT(sb + OFF_MBAR + 8, 129);
    }
    __syncthreads();

#define G1_STAGE(cc) do { \
        int _s = (cc) & 1; \
        uint32_t _fb = sb + OFF_MBAR + _s * 8; \
        MBAR_EXPECT(_fb, 128); \
        BULK_G2S(sb + OFF_AP1 + _s * ASLOT + tid * PITCH_A, arow + (cc) * 128, 128, _fb); \
        if (tid == 0) { \
            MBAR_EXPECT(_fb, 16384); \
            uint32_t _raw = sb + OFF_RAW1 + _s * 16384; \
            TMA2D(_raw, &bmap, (cc) * 32, y0, _fb); \
            TMA2D(_raw + 8192, &bmap, (cc) * 32, y1, _fb); \
        } \
    } while (0)

    G1_STAGE(0);
    G1_STAGE(1);
    MBAR_WAIT(sb + OFF_MBAR, 0);
    convert_b(smem, OFF_RAW1, OFF_BP1, 0, tid);
    __syncthreads();

    for (int c = 0; c < NC1; c++) {
        int slot = c & 1;
        mma_phase_g1(sb, slot, lane, wm, brow, acc);
        if (c + 1 < NC1) {
            int ns = (c + 1) & 1;
            MBAR_WAIT(sb + OFF_MBAR + ns * 8, ((c + 1) >> 1) & 1);
            convert_b(smem, OFF_RAW1, OFF_BP1, ns, tid);
        }
        __syncthreads();
        if (c + 2 < NC1) G1_STAGE(c + 2);
    }
#undef G1_STAGE

    __syncthreads();
    char* stage = smem + OFF_BP1;   // 2*BPAIR = exactly the staging footprint
#pragma unroll
    for (int i = 0; i < 4; i++)
#pragma unroll
        for (int jt = 0; jt < 4; jt++) {
            float* dg = acc[i * 8 + jt];
            float* du = acc[i * 8 + jt + 4];
            int fl = wn * 32 + jt * 8 + 2 * (lane & 3);
            int cf = fl >> 5, c32 = fl & 31;
            int j1 = wm * 64 + i * 16 + (lane >> 2);
#pragma unroll
            for (int rs = 0; rs < 2; rs++) {
                float a0 = silu(dg[rs * 2 + 0]) * du[rs * 2 + 0];
                float a1 = silu(dg[rs * 2 + 1]) * du[rs * 2 + 1];
                uint32_t hp, lp;
                asm("cvt.rn.bf16x2.f32 %0, %1, %2;" : "=r"(hp) : "f"(a1), "f"(a0));
                float hh0 = __uint_as_float(hp << 16), hh1 = __uint_as_float(hp & 0xFFFF0000u);
                asm("cvt.rn.bf16x2.f32 %0, %1, %2;" : "=r"(lp) : "f"(a1 - hh1), "f"(a0 - hh0));
                char* p0 = stage + cf * BPAIR + (j1 + rs * 8) * PITCH_B + c32 * 2;
                *(uint32_t*)p0 = hp;
                *(uint32_t*)(p0 + PLANE_B) = lp;
            }
        }
    __syncthreads();
    char* dst = g_act + (size_t)tile * ACT_TILE + (size_t)(fbase >> 5) * BPAIR;
#pragma unroll
    for (int i = 0; i < 20; i++) {
        int idx = tid + i * 128;
        *(uint4*)(dst + (size_t)idx * 16) = *(const uint4*)(stage + idx * 16);
    }
}

// ================= GEMM2 (R14 core, AP slots sized BPAIR) =================
__global__ __launch_bounds__(128, 1) void gemm2_mma(const __grid_constant__ CUtensorMap bmap) {
    const int e  = blockIdx.y >> 3;
    const int mt = blockIdx.y & 7;
    if (mt >= g_ntiles[e]) return;
    const int rbeg = g_offset[e], rend = g_offset[e + 1];
    const int row0 = rbeg + mt * 128;
    const int hbase = blockIdx.x * 128;
    const int tile = g_tile_base[e] + mt;

    extern __shared__ __align__(16) char smem[];
    const uint32_t sb = smem_u32(smem);
    const int tid = threadIdx.x, lane = tid & 31;
    const int wm = (tid >> 5) & 1, wn = tid >> 6;

    int brow[4];
#pragma unroll
    for (int j2 = 0; j2 < 4; j2++) brow[j2] = wn * 64 + j2 * 16;

    const char* asrc = g_act + (size_t)tile * ACT_TILE;
    const int y0 = e * H + hbase;

    float acc[32][4];
#pragma unroll
    for (int i = 0; i < 32; i++)
#pragma unroll
        for (int j = 0; j < 4; j++) acc[i][j] = 0.f;

    if (tid == 0) {
        MBAR_INIT(sb + OFF_MBAR, 1);
        MBAR_INIT(sb + OFF_MBAR + 8, 1);
    }
    __syncthreads();

#define G2_STAGE(cc) do { \
        int _s = (cc) & 1; \
        uint32_t _fb = sb + OFF_MBAR + _s * 8; \
        MBAR_EXPECT(_fb, BPAIR + 16384); \
        BULK_G2S(sb + OFF_AP2 + _s * BPAIR, asrc + (size_t)(cc) * BPAIR, BPAIR, _fb); \
        TMA2D(sb + OFF_RAW2 + _s * 16384, &bmap, (cc) * 32, y0, _fb); \
    } while (0)

    if (tid == 0) { G2_STAGE(0); G2_STAGE(1); }
    MBAR_WAIT(sb + OFF_MBAR, 0);
    convert_b(smem, OFF_RAW2, OFF_BP2, 0, tid);
    __syncthreads();

    for (int c = 0; c < NC2; c++) {
        int slot = c & 1;
        mma_phase_g2(sb, slot, lane, wm, brow, acc);
        if (c + 1 < NC2) {
            int ns = (c + 1) & 1;
            MBAR_WAIT(sb + OFF_MBAR + ns * 8, ((c + 1) >> 1) & 1);
            convert_b(smem, OFF_RAW2, OFF_BP2, ns, tid);
        }
        __syncthreads();
        if (tid == 0 && c + 2 < NC2) G2_STAGE(c + 2);
    }
#undef G2_STAGE

#pragma unroll
    for (int i = 0; i < 4; i++)
#pragma unroll
        for (int jt = 0; jt < 8; jt++) {
            float* d = acc[i * 8 + jt];
            int hcol = hbase + wn * 64 + jt * 8 + 2 * (lane & 3);
            int r1 = row0 + wm * 64 + i * 16 + (lane >> 2);
            if (r1 < rend)
                *(float2*)(g_y + (size_t)r1 * H + hcol) = make_float2(d[0], d[1]);
            if (r1 + 8 < rend)
                *(float2*)(g_y + (size_t)(r1 + 8) * H + hcol) = make_float2(d[2], d[3]);
        }
}

// ---------------- gather ----------------
__global__ void gather_kernel(float* __restrict__ out) {
    int t = blockIdx.x;
    __shared__ float ws[K];
    __shared__ int   rs[K];
    if (threadIdx.x < K) {
        ws[threadIdx.x] = g_topk_w[t * K + threadIdx.x];
        rs[threadIdx.x] = g_row_of[t * K + threadIdx.x];
    }
    __syncthreads();
    int h = threadIdx.x * 4;
    float4 acc = make_float4(0.f, 0.f, 0.f, 0.f);
#pragma unroll
    for (int k = 0; k < K; k++) {
        float4 v = *(const float4*)(g_y + (size_t)rs[k] * H + h);
        float w = ws[k];
        acc.x += w * v.x;
        acc.y += w * v.y;
        acc.z += w * v.z;
        acc.w += w * v.w;
    }
    *(float4*)(out + (size_t)t * H + h) = acc;
}

// ---------------- host ----------------
typedef CUresult (*encode_fn_t)(CUtensorMap*, CUtensorMapDataType, cuuint32_t, void*,
                                const cuuint64_t*, const cuuint64_t*, const cuuint32_t*,
                                const cuuint32_t*, CUtensorMapInterleave, CUtensorMapSwizzle,
                                CUtensorMapL2promotion, CUtensorMapFloatOOBfill);

extern "C" void kernel_launch(void* const* d_in, const int* in_sizes, int n_in,
                              void* d_out, int out_size) {
    const float* hs = (const float*)d_in[0];
    const float* gw = (const float*)d_in[1];
    const float* w1 = (const float*)d_in[2];
    const float* w2 = (const float*)d_in[3];
    float* out = (float*)d_out;

    static encode_fn_t enc = nullptr;
    static bool attr_done = false;
    if (!attr_done) {
        cudaFuncSetAttribute(gemm1_mma, cudaFuncAttributeMaxDynamicSharedMemorySize, SMEM_TOTAL);
        cudaFuncSetAttribute(gemm2_mma, cudaFuncAttributeMaxDynamicSharedMemorySize, SMEM_TOTAL);
        void* hlib = dlopen("libcuda.so.1", RTLD_NOW | RTLD_GLOBAL);
        if (!hlib) hlib = dlopen("libcuda.so", RTLD_NOW | RTLD_GLOBAL);
        if (hlib) enc = (encode_fn_t)dlsym(hlib, "cuTensorMapEncodeTiled");
        attr_done = true;
    }

    CUtensorMap m1, m2;
    {
        cuuint64_t dims[2] = {(cuuint64_t)H, (cuuint64_t)E * 2 * F};
        cuuint64_t strides[1] = {(cuuint64_t)H * 4};
        cuuint32_t box[2] = {32, 64};
        cuuint32_t es[2] = {1, 1};
        enc(&m1, CU_TENSOR_MAP_DATA_TYPE_FLOAT32, 2, (void*)w1, dims, strides, box, es,
            CU_TENSOR_MAP_INTERLEAVE_NONE, CU_TENSOR_MAP_SWIZZLE_NONE,
            CU_TENSOR_MAP_L2_PROMOTION_L2_128B, CU_TENSOR_MAP_FLOAT_OOB_FILL_NONE);
    }
    {
        cuuint64_t dims[2] = {(cuuint64_t)F, (cuuint64_t)E * H};
        cuuint64_t strides[1] = {(cuuint64_t)F * 4};
        cuuint32_t box[2] = {32, 128};
        cuuint32_t es[2] = {1, 1};
        enc(&m2, CU_TENSOR_MAP_DATA_TYPE_FLOAT32, 2, (void*)w2, dims, strides, box, es,
            CU_TENSOR_MAP_INTERLEAVE_NONE, CU_TENSOR_MAP_SWIZZLE_NONE,
            CU_TENSOR_MAP_L2_PROMOTION_L2_128B, CU_TENSOR_MAP_FLOAT_OOB_FILL_NONE);
    }

    router_kernel<<<T / 4, 128>>>(hs, gw);
    bucket_kernel<<<1, 1024>>>();
    hs_pack_kernel<<<T * H / 8 / 256, 256>>>(hs);
    gemm1_mma<<<dim3(F / 64, E * 8), 128, SMEM_TOTAL>>>(m1);
    gemm2_mma<<<dim3(H / 128, E * 8), 128, SMEM_TOTAL>>>(m2);
    gather_kernel<<<T, 256>>>(out);
}